// round 12
// baseline (speedup 1.0000x reference)
#include <cuda_runtime.h>

#define NB 32
#define NC 64
#define SSZ 112
#define NSP 12544          // 112*112
#define PLANE_TOT 25690112 // 32*64*12544
#define KPAD 116
#define KPAD2 232          // pair-interleaved row: [i*2 + parity], i<112, padded to 116*2
#define EPSV 1e-5f
#define NBN 401408.0f      // 32*12544

// ---------------- scratch (device globals; no allocs allowed) ----------------
__device__ float g_qf[PLANE_TOT];
__device__ float g_ql[PLANE_TOT];
__device__ float g_kf[PLANE_TOT];
__device__ float g_kl[PLANE_TOT];
__device__ float g_attn[PLANE_TOT];
__device__ float g_yfad[PLANE_TOT];
__device__ float g_ylfs[PLANE_TOT];
__device__ float g_pstat[256];
__device__ float g_bn1[384];
__device__ float g_ys [NB * 128];
__device__ float g_yss[NB * 128];
__device__ float g_ap [NB * 128];
__device__ float g_mpool[NB * 128];
__device__ float g_Acoef[2 * NB * NC];
__device__ float g_Bcoef[2 * NC];

// ---------------- helpers ----------------
typedef unsigned long long ull;

__device__ __forceinline__ void fma2(ull& d, ull a, ull b) {
    asm("fma.rn.f32x2 %0, %1, %2, %0;" : "+l"(d) : "l"(a), "l"(b));
}
__device__ __forceinline__ ull pack2(float lo, float hi) {
    ull r; asm("mov.b64 %0, {%1, %2};" : "=l"(r) : "f"(lo), "f"(hi)); return r;
}
__device__ __forceinline__ float hadd2(ull v) {
    float lo, hi; asm("mov.b64 {%0, %1}, %2;" : "=f"(lo), "=f"(hi) : "l"(v));
    return lo + hi;
}
__device__ __forceinline__ float warpSum(float v) {
    #pragma unroll
    for (int o = 16; o > 0; o >>= 1) v += __shfl_xor_sync(0xffffffffu, v, o);
    return v;
}
__device__ __forceinline__ float warpMax(float v) {
    #pragma unroll
    for (int o = 16; o > 0; o >>= 1) v = fmaxf(v, __shfl_xor_sync(0xffffffffu, v, o));
    return v;
}

// ---------------- K1: projection GEMMs (4x conv1x1), f32x2-packed ----------------
// grid (196, 32), 256 threads, dyn smem 99328 B
__global__ void k1_proj(const float* __restrict__ rgb, const float* __restrict__ fre,
                        const float* __restrict__ wqf, const float* __restrict__ bqf,
                        const float* __restrict__ wql, const float* __restrict__ bql,
                        const float* __restrict__ wkf, const float* __restrict__ bkf,
                        const float* __restrict__ wkl, const float* __restrict__ bkl) {
    extern __shared__ float sm[];
    float* Wsm = sm;              // 16384
    float* bsm = sm + 16384;      // 256
    float* Xr  = sm + 16640;      // 4096
    float* Xf  = sm + 20736;      // 4096

    int tid = threadIdx.x;
    int b = blockIdx.y, tile = blockIdx.x;

    // fold former k0: zero the atomic stat buffer (consumed by k2, after this kernel completes)
    if (blockIdx.x == 0 && blockIdx.y == 0) g_pstat[tid] = 0.0f;

    for (int idx = tid; idx < 4096; idx += 256) {
        Wsm[idx]         = wqf[idx];
        Wsm[4096 + idx]  = wql[idx];
        Wsm[8192 + idx]  = wkf[idx];
        Wsm[12288 + idx] = wkl[idx];
    }
    if (tid < 64) {
        bsm[tid]       = bqf[tid];
        bsm[64 + tid]  = bql[tid];
        bsm[128 + tid] = bkf[tid];
        bsm[192 + tid] = bkl[tid];
    }
    int p0 = tile * 64;
    const float* rb = rgb + b * NC * NSP + p0;
    const float* fb = fre + b * NC * NSP + p0;
    for (int idx = tid; idx < 4096; idx += 256) {
        int k = idx >> 6, p = idx & 63;
        Xr[idx] = rb[k * NSP + p];
        Xf[idx] = fb[k * NSP + p];
    }
    __syncthreads();

    int og = tid >> 4, pg = tid & 15;
    int o0 = og * 16, pl = pg * 4;
    int m = og >> 2;
    const float* X = (m & 1) ? Xf : Xr;

    ull acc2[16][4];
    #pragma unroll
    for (int oo = 0; oo < 16; oo++)
        #pragma unroll
        for (int p = 0; p < 4; p++) acc2[oo][p] = 0ull;

    for (int k = 0; k < 64; k += 2) {
        float4 xa = *(const float4*)&X[k * 64 + pl];
        float4 xb = *(const float4*)&X[(k + 1) * 64 + pl];
        ull xp0 = pack2(xa.x, xb.x);
        ull xp1 = pack2(xa.y, xb.y);
        ull xp2 = pack2(xa.z, xb.z);
        ull xp3 = pack2(xa.w, xb.w);
        #pragma unroll
        for (int oo = 0; oo < 16; oo++) {
            ull wv = *(const ull*)&Wsm[(o0 + oo) * 64 + k];  // (W[o][k], W[o][k+1])
            fma2(acc2[oo][0], wv, xp0);
            fma2(acc2[oo][1], wv, xp1);
            fma2(acc2[oo][2], wv, xp2);
            fma2(acc2[oo][3], wv, xp3);
        }
    }

    float* dst = (m == 0) ? g_qf : (m == 1) ? g_ql : (m == 2) ? g_kf : g_kl;
    int oc0 = o0 & 63;
    #pragma unroll
    for (int oo = 0; oo < 16; oo++) {
        float bv = bsm[o0 + oo];
        float4 v;
        v.x = hadd2(acc2[oo][0]) + bv;
        v.y = hadd2(acc2[oo][1]) + bv;
        v.z = hadd2(acc2[oo][2]) + bv;
        v.w = hadd2(acc2[oo][3]) + bv;
        *(float4*)&dst[(b * NC + oc0 + oo) * NSP + p0 + pl] = v;
    }
}

// ---------------- K2: attention GEMM (f32x2, pair-interleaved smem) + softmax + stats ----
// grid 2048, 256 threads, dyn smem 207872 B
__global__ void k2_attn(const float* __restrict__ rgb, const float* __restrict__ fre) {
    extern __shared__ float sm[];
    float* Ks = sm;                  // [112 kpairs][KPAD2]: Ks[pr*232 + j*2 + parity]
    float* Qs = sm + 112 * KPAD2;    // same layout; reused as logits [112][KPAD]

    int bc = blockIdx.x;
    int tid = threadIdx.x;
    int base = bc * NSP;

    for (int idx = tid; idx < NSP; idx += 256) {
        int j = idx / SSZ;
        int k = idx - j * SSZ;
        int pr = k >> 1, pa = k & 1;
        int off  = pr * KPAD2 + j * 2 + pa;          // k in [0,112)  -> pairs 0..55
        int off2 = (56 + pr) * KPAD2 + j * 2 + pa;   // k+112         -> pairs 56..111
        Ks[off]  = g_kf[base + idx];
        Ks[off2] = g_kl[base + idx];
        Qs[off]  = g_qf[base + idx];
        Qs[off2] = g_ql[base + idx];
    }
    __syncthreads();

    int ti = tid >> 4, tj = tid & 15;
    int i0 = ti * 7, j0 = tj * 7;
    ull acc2[7][7];
    #pragma unroll
    for (int r = 0; r < 7; r++)
        #pragma unroll
        for (int s = 0; s < 7; s++) acc2[r][s] = 0ull;

    for (int kp = 0; kp < 112; kp++) {
        const float* qrow = Qs + kp * KPAD2;
        const float* krow = Ks + kp * KPAD2;
        ull va[7], vb[7];
        #pragma unroll
        for (int r = 0; r < 7; r++) va[r] = *(const ull*)&qrow[(i0 + r) * 2];
        #pragma unroll
        for (int s = 0; s < 7; s++) vb[s] = *(const ull*)&krow[(j0 + s) * 2];
        #pragma unroll
        for (int r = 0; r < 7; r++)
            #pragma unroll
            for (int s = 0; s < 7; s++) fma2(acc2[r][s], va[r], vb[s]);
    }
    __syncthreads();   // GEMM reads done

    float* Ls = Qs;    // logits [112][KPAD]
    #pragma unroll
    for (int r = 0; r < 7; r++)
        #pragma unroll
        for (int s = 0; s < 7; s++)
            Ls[(i0 + r) * KPAD + j0 + s] = hadd2(acc2[r][s]);
    __syncthreads();

    // softmax: 8 warps x 14 rows
    int w = tid >> 5, lane = tid & 31;
    for (int rr = 0; rr < 14; rr++) {
        int i = w * 14 + rr;
        float* row = Ls + i * KPAD;
        float mx = -1e30f;
        for (int j = lane; j < SSZ; j += 32) mx = fmaxf(mx, row[j]);
        mx = warpMax(mx);
        float s = 0.f;
        for (int j = lane; j < SSZ; j += 32) { float e = __expf(row[j] - mx); row[j] = e; s += e; }
        s = warpSum(s);
        float inv = 1.0f / s;
        for (int j = lane; j < SSZ; j += 32) row[j] *= inv;
    }
    __syncthreads();

    const float* rp = rgb + base;
    const float* fp = fre + base;
    float s1 = 0.f, q1 = 0.f, s2 = 0.f, q2 = 0.f;
    for (int idx = tid; idx < NSP; idx += 256) {
        int i = idx / SSZ;
        int j = idx - i * SSZ;
        float a = Ls[i * KPAD + j];
        g_attn[base + idx] = a;
        float p1 = fp[idx] * a;
        float p2 = rp[idx] * a;
        s1 += p1; q1 += p1 * p1;
        s2 += p2; q2 += p2 * p2;
    }
    s1 = warpSum(s1); q1 = warpSum(q1); s2 = warpSum(s2); q2 = warpSum(q2);
    if (lane == 0) {
        int c = bc & 63;
        atomicAdd(&g_pstat[c],       s1);
        atomicAdd(&g_pstat[64 + c],  q1);
        atomicAdd(&g_pstat[128 + c], s2);
        atomicAdd(&g_pstat[192 + c], q2);
    }
}

// ---------------- K2.5: fold BN1 statistics ----------------
__global__ void k25_bn1(const float* __restrict__ lfs_gamma, const float* __restrict__ fad_gamma,
                        const float* __restrict__ fad_cw, const float* __restrict__ fad_bg,
                        const float* __restrict__ fad_bb,
                        const float* __restrict__ lfs_cw, const float* __restrict__ lfs_bg,
                        const float* __restrict__ lfs_bb) {
    int c = threadIdx.x;
    if (c >= 64) return;
    float cL = 2.0f / (1.0f + expf(-lfs_gamma[0])) - 1.0f;
    float cF = 2.0f / (1.0f + expf(-fad_gamma[0])) - 1.0f;

    float s = g_pstat[c], q = g_pstat[64 + c];
    float mp = s / NBN;
    float varp = q / NBN - mp * mp;
    float a = cL * fad_cw[c];
    float inv = rsqrtf(a * a * varp + EPSV);
    g_bn1[c]        = mp;
    g_bn1[64 + c]   = a * inv * fad_bg[c];
    g_bn1[128 + c]  = fad_bb[c];

    s = g_pstat[128 + c]; q = g_pstat[192 + c];
    mp = s / NBN;
    varp = q / NBN - mp * mp;
    a = cF * lfs_cw[c];
    inv = rsqrtf(a * a * varp + EPSV);
    g_bn1[192 + c] = mp;
    g_bn1[256 + c] = a * inv * lfs_bg[c];
    g_bn1[320 + c] = lfs_bb[c];
}

// ---------------- K3: y compute + per-plane stats + multiscale pooling ----------------
__device__ __forceinline__ void blockReduceSumMax(float sv, float mv, float* outS, float* outM,
                                                  volatile float* sbuf) {
    sv = warpSum(sv);
    mv = warpMax(mv);
    int w = threadIdx.x >> 5, lane = threadIdx.x & 31;
    __syncthreads();
    if (lane == 0) { sbuf[w] = sv; sbuf[8 + w] = mv; }
    __syncthreads();
    if (threadIdx.x == 0) {
        float s = 0.f, m = -1e30f;
        for (int i = 0; i < 8; i++) { s += sbuf[i]; m = fmaxf(m, sbuf[8 + i]); }
        sbuf[0] = s; sbuf[8] = m;
    }
    __syncthreads();
    *outS = sbuf[0];
    *outM = sbuf[8];
}

template <int K, int NW>
__device__ __forceinline__ void poolStats(const float* yp, float* ws, float* wm) {
    float ts = 0.f, tm = -1e30f;
    for (int wdx = threadIdx.x; wdx < NW * NW; wdx += 256) {
        int wy = (wdx / NW) * K;
        int wx = (wdx - (wdx / NW) * NW) * K;
        float s = 0.f;
        #pragma unroll
        for (int dy = 0; dy < K; dy++)
            #pragma unroll
            for (int dx = 0; dx < K; dx++)
                s += yp[(wy + dy) * SSZ + wx + dx];
        ts += s;
        tm = fmaxf(tm, s);
    }
    *ws = ts;
    *wm = tm;
}

// grid (128, 32), 256 threads, dyn smem 50176 B
__global__ void k3_ypool(const float* __restrict__ rgb, const float* __restrict__ fre,
                         const float* __restrict__ lin1, const float* __restrict__ lin2) {
    extern __shared__ float yp[];
    __shared__ float sbuf[16];

    int c2 = blockIdx.x, b = blockIdx.y, tid = threadIdx.x;
    int path = (c2 >= 64);
    int c = c2 & 63;
    int base = (b * NC + c) * NSP;

    float mp, sc, of;
    if (!path) { mp = g_bn1[c];       sc = g_bn1[64 + c];  of = g_bn1[128 + c]; }
    else       { mp = g_bn1[192 + c]; sc = g_bn1[256 + c]; of = g_bn1[320 + c]; }
    float* ydst = path ? g_ylfs : g_yfad;

    float ys = 0.f, yss = 0.f;
    for (int idx = tid; idx < NSP; idx += 256) {
        float a = g_attn[base + idx];
        float r = rgb[base + idx];
        float f = fre[base + idx];
        float y = path ? (f + (r * a - mp) * sc + of)
                       : (r + (f * a - mp) * sc + of);
        yp[idx] = y;
        ydst[base + idx] = y;
        ys += y;
        yss += y * y;
    }
    {
        float bs, bm;
        blockReduceSumMax(ys, -1e30f, &bs, &bm, sbuf);
        if (tid == 0) g_ys[b * 128 + c2] = bs;
        blockReduceSumMax(yss, -1e30f, &bs, &bm, sbuf);
        if (tid == 0) g_yss[b * 128 + c2] = bs;
    }
    __syncthreads();

    float l10 = lin1[0], l11 = lin1[1], l12 = lin1[2];
    float l20 = lin2[0], l21 = lin2[1], l22 = lin2[2];
    float apv = 0.f, mpv = 0.f;
    float ws, wm, bs, bm;

    poolStats<3, 37>(yp, &ws, &wm);
    blockReduceSumMax(ws, wm, &bs, &bm, sbuf);
    apv += l10 * (bs / (37.f * 37.f * 9.f));
    mpv += l20 * (bm / 9.f);

    poolStats<5, 22>(yp, &ws, &wm);
    blockReduceSumMax(ws, wm, &bs, &bm, sbuf);
    apv += l11 * (bs / (22.f * 22.f * 25.f));
    mpv += l21 * (bm / 25.f);

    poolStats<7, 16>(yp, &ws, &wm);
    blockReduceSumMax(ws, wm, &bs, &bm, sbuf);
    apv += l12 * (bs / (16.f * 16.f * 49.f));
    mpv += l22 * (bm / 49.f);

    if (tid == 0) {
        g_ap[b * 128 + c2]    = apv;
        g_mpool[b * 128 + c2] = mpv;
    }
}

// ---------------- K4: MLP channel attention + analytic BN2 coefficients ----------------
__global__ void k4_mlp(const float* __restrict__ w1, const float* __restrict__ w2,
                       const float* __restrict__ rgb_cw, const float* __restrict__ rgb_cb,
                       const float* __restrict__ rgb_bg, const float* __restrict__ rgb_bb,
                       const float* __restrict__ fre_cw, const float* __restrict__ fre_cb,
                       const float* __restrict__ fre_bg, const float* __restrict__ fre_bb) {
    __shared__ float ca[NB][128];
    __shared__ float hsum[16];
    int tid = threadIdx.x;

    for (int b = 0; b < NB; b++) {
        if (tid < 16) {
            float ha = 0.f, hm = 0.f;
            for (int cth = 0; cth < 128; cth++) {
                float wv = w1[tid * 128 + cth];
                ha = fmaf(wv, g_ap[b * 128 + cth], ha);
                hm = fmaf(wv, g_mpool[b * 128 + cth], hm);
            }
            hsum[tid] = fmaxf(ha, 0.f) + fmaxf(hm, 0.f);
        }
        __syncthreads();
        float o = 0.f;
        #pragma unroll
        for (int r = 0; r < 16; r++) o = fmaf(w2[tid * 16 + r], hsum[r], o);
        ca[b][tid] = 1.0f / (1.0f + expf(-o));
        __syncthreads();
    }

    int path = (tid >= 64);
    int c = tid & 63;
    float cw = path ? fre_cw[c] : rgb_cw[c];
    float cb = path ? fre_cb[c] : rgb_cb[c];
    float bg = path ? fre_bg[c] : rgb_bg[c];
    float bb = path ? fre_bb[c] : rgb_bb[c];

    float s1 = 0.f, s2 = 0.f;
    for (int b = 0; b < NB; b++) {
        float cav = ca[b][tid];
        s1 = fmaf(cav, g_ys[b * 128 + tid], s1);
        s2 = fmaf(cav * cav, g_yss[b * 128 + tid], s2);
    }
    float meanz = (cw * s1) / NBN + cb;
    float Ezz = (cw * cw * s2 + 2.0f * cw * cb * s1) / NBN + cb * cb;
    float var = Ezz - meanz * meanz;
    float inv = rsqrtf(var + EPSV);
    g_Bcoef[tid] = (cb - meanz) * inv * bg + bb;
    for (int b = 0; b < NB; b++)
        g_Acoef[path * (NB * NC) + b * NC + c] = 1.0f + ca[b][tid] * cw * inv * bg;
}

// ---------------- K5: streaming output ----------------
__global__ void k5_out(float* __restrict__ out) {
    int c = blockIdx.x, b = blockIdx.y, path = blockIdx.z;
    int plane = (b * NC + c) * NSP;
    const float* y = (path ? g_ylfs : g_yfad) + plane;
    float A = g_Acoef[path * (NB * NC) + b * NC + c];
    float Bv = g_Bcoef[path * NC + c];
    float* o = out + (size_t)path * PLANE_TOT + plane;
    for (int idx = threadIdx.x; idx < NSP / 4; idx += 256) {
        float4 v = ((const float4*)y)[idx];
        v.x = fmaf(v.x, A, Bv);
        v.y = fmaf(v.y, A, Bv);
        v.z = fmaf(v.z, A, Bv);
        v.w = fmaf(v.w, A, Bv);
        ((float4*)o)[idx] = v;
    }
}

// ---------------- launch ----------------
extern "C" void kernel_launch(void* const* d_in, const int* in_sizes, int n_in,
                              void* d_out, int out_size) {
    const float* rgb       = (const float*)d_in[0];
    const float* fre       = (const float*)d_in[1];
    const float* wq_fad    = (const float*)d_in[2];
    const float* bq_fad    = (const float*)d_in[3];
    const float* wq_lfs    = (const float*)d_in[4];
    const float* bq_lfs    = (const float*)d_in[5];
    const float* wk_fad    = (const float*)d_in[6];
    const float* bk_fad    = (const float*)d_in[7];
    const float* wk_lfs    = (const float*)d_in[8];
    const float* bk_lfs    = (const float*)d_in[9];
    const float* fad_gamma = (const float*)d_in[10];
    const float* lfs_gamma = (const float*)d_in[11];
    const float* fad_cw    = (const float*)d_in[12];
    const float* fad_bg    = (const float*)d_in[14];
    const float* fad_bb    = (const float*)d_in[15];
    const float* lfs_cw    = (const float*)d_in[16];
    const float* lfs_bg    = (const float*)d_in[18];
    const float* lfs_bb    = (const float*)d_in[19];
    const float* lin1_w    = (const float*)d_in[20];
    const float* lin2_w    = (const float*)d_in[21];
    const float* mlp_w1    = (const float*)d_in[22];
    const float* mlp_w2    = (const float*)d_in[23];
    const float* rgb_cw    = (const float*)d_in[24];
    const float* rgb_cb    = (const float*)d_in[25];
    const float* rgb_bg    = (const float*)d_in[26];
    const float* rgb_bb    = (const float*)d_in[27];
    const float* fre_cw    = (const float*)d_in[28];
    const float* fre_cb    = (const float*)d_in[29];
    const float* fre_bg    = (const float*)d_in[30];
    const float* fre_bb    = (const float*)d_in[31];

    cudaFuncSetAttribute(k1_proj,  cudaFuncAttributeMaxDynamicSharedMemorySize, 99328);
    cudaFuncSetAttribute(k2_attn,  cudaFuncAttributeMaxDynamicSharedMemorySize, 207872);
    cudaFuncSetAttribute(k3_ypool, cudaFuncAttributeMaxDynamicSharedMemorySize, 50176);

    k1_proj<<<dim3(196, NB), 256, 99328>>>(rgb, fre, wq_fad, bq_fad, wq_lfs, bq_lfs,
                                           wk_fad, bk_fad, wk_lfs, bk_lfs);
    k2_attn<<<2048, 256, 207872>>>(rgb, fre);
    k25_bn1<<<1, 64>>>(lfs_gamma, fad_gamma, fad_cw, fad_bg, fad_bb,
                       lfs_cw, lfs_bg, lfs_bb);
    k3_ypool<<<dim3(128, NB), 256, 50176>>>(rgb, fre, lin1_w, lin2_w);
    k4_mlp<<<1, 128>>>(mlp_w1, mlp_w2, rgb_cw, rgb_cb, rgb_bg, rgb_bb,
                       fre_cw, fre_cb, fre_bg, fre_bb);
    k5_out<<<dim3(NC, NB, 2), 256>>>((float*)d_out);
}

// round 13
// speedup vs baseline: 1.3010x; 1.3010x over previous
#include <cuda_runtime.h>

#define NB 32
#define NC 64
#define SSZ 112
#define NSP 12544          // 112*112
#define PLANE_TOT 25690112 // 32*64*12544
#define KPAD 116
#define EPSV 1e-5f
#define NBN 401408.0f      // 32*12544

// ---------------- scratch (device globals; no allocs allowed) ----------------
__device__ float g_qf[PLANE_TOT];
__device__ float g_ql[PLANE_TOT];
__device__ float g_kf[PLANE_TOT];
__device__ float g_kl[PLANE_TOT];
__device__ float g_attn[PLANE_TOT];
__device__ float g_yfad[PLANE_TOT];
__device__ float g_ylfs[PLANE_TOT];
__device__ float g_pstat[256];
__device__ float g_bn1[384];
__device__ float g_ys [NB * 128];
__device__ float g_yss[NB * 128];
__device__ float g_ap [NB * 128];
__device__ float g_mpool[NB * 128];
__device__ float g_Acoef[2 * NB * NC];
__device__ float g_Bcoef[2 * NC];

// ---------------- helpers ----------------
__device__ __forceinline__ float warpSum(float v) {
    #pragma unroll
    for (int o = 16; o > 0; o >>= 1) v += __shfl_xor_sync(0xffffffffu, v, o);
    return v;
}
__device__ __forceinline__ float warpMax(float v) {
    #pragma unroll
    for (int o = 16; o > 0; o >>= 1) v = fmaxf(v, __shfl_xor_sync(0xffffffffu, v, o));
    return v;
}

// ---------------- K0a/K0b: zero stat buffer (split so k2 lands at capture idx 3) ----
__global__ void k0a_zero() { g_pstat[threadIdx.x] = 0.0f; }          // 128 threads: [0,128)
__global__ void k0b_zero() { g_pstat[128 + threadIdx.x] = 0.0f; }    // 128 threads: [128,256)

// ---------------- K1: projection GEMMs (4x conv1x1), scalar (measured-good) --------
// grid (196, 32), 256 threads, dyn smem 99328 B
__global__ void k1_proj(const float* __restrict__ rgb, const float* __restrict__ fre,
                        const float* __restrict__ wqf, const float* __restrict__ bqf,
                        const float* __restrict__ wql, const float* __restrict__ bql,
                        const float* __restrict__ wkf, const float* __restrict__ bkf,
                        const float* __restrict__ wkl, const float* __restrict__ bkl) {
    extern __shared__ float sm[];
    float* Wsm = sm;              // 16384
    float* bsm = sm + 16384;      // 256
    float* Xr  = sm + 16640;      // 4096
    float* Xf  = sm + 20736;      // 4096

    int tid = threadIdx.x;
    int b = blockIdx.y, tile = blockIdx.x;

    for (int idx = tid; idx < 4096; idx += 256) {
        Wsm[idx]         = wqf[idx];
        Wsm[4096 + idx]  = wql[idx];
        Wsm[8192 + idx]  = wkf[idx];
        Wsm[12288 + idx] = wkl[idx];
    }
    if (tid < 64) {
        bsm[tid]       = bqf[tid];
        bsm[64 + tid]  = bql[tid];
        bsm[128 + tid] = bkf[tid];
        bsm[192 + tid] = bkl[tid];
    }
    int p0 = tile * 64;
    const float* rb = rgb + b * NC * NSP + p0;
    const float* fb = fre + b * NC * NSP + p0;
    for (int idx = tid; idx < 4096; idx += 256) {
        int k = idx >> 6, p = idx & 63;
        Xr[idx] = rb[k * NSP + p];
        Xf[idx] = fb[k * NSP + p];
    }
    __syncthreads();

    int og = tid >> 4, pg = tid & 15;
    int o0 = og * 16, pl = pg * 4;
    int m = og >> 2;
    const float* X = (m & 1) ? Xf : Xr;

    float4 acc[16];
    #pragma unroll
    for (int oo = 0; oo < 16; oo++) acc[oo] = make_float4(0.f, 0.f, 0.f, 0.f);

    for (int k = 0; k < 64; k += 4) {
        float4 x0 = *(const float4*)&X[(k + 0) * 64 + pl];
        float4 x1 = *(const float4*)&X[(k + 1) * 64 + pl];
        float4 x2 = *(const float4*)&X[(k + 2) * 64 + pl];
        float4 x3 = *(const float4*)&X[(k + 3) * 64 + pl];
        #pragma unroll
        for (int oo = 0; oo < 16; oo++) {
            float4 w4 = *(const float4*)&Wsm[(o0 + oo) * 64 + k];
            float4 a = acc[oo];
            a.x = fmaf(w4.x, x0.x, a.x); a.y = fmaf(w4.x, x0.y, a.y);
            a.z = fmaf(w4.x, x0.z, a.z); a.w = fmaf(w4.x, x0.w, a.w);
            a.x = fmaf(w4.y, x1.x, a.x); a.y = fmaf(w4.y, x1.y, a.y);
            a.z = fmaf(w4.y, x1.z, a.z); a.w = fmaf(w4.y, x1.w, a.w);
            a.x = fmaf(w4.z, x2.x, a.x); a.y = fmaf(w4.z, x2.y, a.y);
            a.z = fmaf(w4.z, x2.z, a.z); a.w = fmaf(w4.z, x2.w, a.w);
            a.x = fmaf(w4.w, x3.x, a.x); a.y = fmaf(w4.w, x3.y, a.y);
            a.z = fmaf(w4.w, x3.z, a.z); a.w = fmaf(w4.w, x3.w, a.w);
            acc[oo] = a;
        }
    }

    float* dst = (m == 0) ? g_qf : (m == 1) ? g_ql : (m == 2) ? g_kf : g_kl;
    int oc0 = o0 & 63;
    #pragma unroll
    for (int oo = 0; oo < 16; oo++) {
        float bv = bsm[o0 + oo];
        float4 v = acc[oo];
        v.x += bv; v.y += bv; v.z += bv; v.w += bv;
        *(float4*)&dst[(b * NC + oc0 + oo) * NSP + p0 + pl] = v;
    }
}

// ---------------- K2: attention GEMM + softmax + product stats (scalar, measured) --
// grid 2048, 256 threads, dyn smem 207872 B
__global__ void k2_attn(const float* __restrict__ rgb, const float* __restrict__ fre) {
    extern __shared__ float sm[];
    float* Ks = sm;                 // [224][KPAD] k-major
    float* Qs = sm + 224 * KPAD;    // [224][KPAD] k-major, reused as logits [112][KPAD]

    int bc = blockIdx.x;
    int tid = threadIdx.x;
    int base = bc * NSP;

    for (int idx = tid; idx < NSP; idx += 256) {
        int j = idx / SSZ;
        int k = idx - j * SSZ;
        Ks[k * KPAD + j]           = g_kf[base + idx];
        Ks[(112 + k) * KPAD + j]   = g_kl[base + idx];
        Qs[k * KPAD + j]           = g_qf[base + idx];
        Qs[(112 + k) * KPAD + j]   = g_ql[base + idx];
    }
    __syncthreads();

    int ti = tid >> 4, tj = tid & 15;
    int i0 = ti * 7, j0 = tj * 7;
    float acc[7][7];
    #pragma unroll
    for (int r = 0; r < 7; r++)
        #pragma unroll
        for (int s = 0; s < 7; s++) acc[r][s] = 0.f;

    #pragma unroll 4
    for (int k = 0; k < 224; k++) {
        float a[7], bv[7];
        #pragma unroll
        for (int r = 0; r < 7; r++) a[r] = Qs[k * KPAD + i0 + r];
        #pragma unroll
        for (int s = 0; s < 7; s++) bv[s] = Ks[k * KPAD + j0 + s];
        #pragma unroll
        for (int r = 0; r < 7; r++)
            #pragma unroll
            for (int s = 0; s < 7; s++) acc[r][s] = fmaf(a[r], bv[s], acc[r][s]);
    }
    __syncthreads();

    float* Ls = Qs;    // logits [112][KPAD]
    #pragma unroll
    for (int r = 0; r < 7; r++)
        #pragma unroll
        for (int s = 0; s < 7; s++) Ls[(i0 + r) * KPAD + j0 + s] = acc[r][s];
    __syncthreads();

    // softmax: 8 warps x 14 rows
    int w = tid >> 5, lane = tid & 31;
    for (int rr = 0; rr < 14; rr++) {
        int i = w * 14 + rr;
        float* row = Ls + i * KPAD;
        float mx = -1e30f;
        for (int j = lane; j < SSZ; j += 32) mx = fmaxf(mx, row[j]);
        mx = warpMax(mx);
        float s = 0.f;
        for (int j = lane; j < SSZ; j += 32) { float e = __expf(row[j] - mx); row[j] = e; s += e; }
        s = warpSum(s);
        float inv = 1.0f / s;
        for (int j = lane; j < SSZ; j += 32) row[j] *= inv;
    }
    __syncthreads();

    const float* rp = rgb + base;
    const float* fp = fre + base;
    float s1 = 0.f, q1 = 0.f, s2 = 0.f, q2 = 0.f;
    for (int idx = tid; idx < NSP; idx += 256) {
        int i = idx / SSZ;
        int j = idx - i * SSZ;
        float a = Ls[i * KPAD + j];
        g_attn[base + idx] = a;
        float p1 = fp[idx] * a;
        float p2 = rp[idx] * a;
        s1 += p1; q1 += p1 * p1;
        s2 += p2; q2 += p2 * p2;
    }
    s1 = warpSum(s1); q1 = warpSum(q1); s2 = warpSum(s2); q2 = warpSum(q2);
    if (lane == 0) {
        int c = bc & 63;
        atomicAdd(&g_pstat[c],       s1);
        atomicAdd(&g_pstat[64 + c],  q1);
        atomicAdd(&g_pstat[128 + c], s2);
        atomicAdd(&g_pstat[192 + c], q2);
    }
}

// ---------------- K2.5: fold BN1 statistics ----------------
__global__ void k25_bn1(const float* __restrict__ lfs_gamma, const float* __restrict__ fad_gamma,
                        const float* __restrict__ fad_cw, const float* __restrict__ fad_bg,
                        const float* __restrict__ fad_bb,
                        const float* __restrict__ lfs_cw, const float* __restrict__ lfs_bg,
                        const float* __restrict__ lfs_bb) {
    int c = threadIdx.x;
    if (c >= 64) return;
    float cL = 2.0f / (1.0f + expf(-lfs_gamma[0])) - 1.0f;
    float cF = 2.0f / (1.0f + expf(-fad_gamma[0])) - 1.0f;

    float s = g_pstat[c], q = g_pstat[64 + c];
    float mp = s / NBN;
    float varp = q / NBN - mp * mp;
    float a = cL * fad_cw[c];
    float inv = rsqrtf(a * a * varp + EPSV);
    g_bn1[c]        = mp;
    g_bn1[64 + c]   = a * inv * fad_bg[c];
    g_bn1[128 + c]  = fad_bb[c];

    s = g_pstat[128 + c]; q = g_pstat[192 + c];
    mp = s / NBN;
    varp = q / NBN - mp * mp;
    a = cF * lfs_cw[c];
    inv = rsqrtf(a * a * varp + EPSV);
    g_bn1[192 + c] = mp;
    g_bn1[256 + c] = a * inv * lfs_bg[c];
    g_bn1[320 + c] = lfs_bb[c];
}

// ---------------- K3: y compute (float4) + per-plane stats + multiscale pooling ----
__device__ __forceinline__ void blockReduceSumMax(float sv, float mv, float* outS, float* outM,
                                                  volatile float* sbuf) {
    sv = warpSum(sv);
    mv = warpMax(mv);
    int w = threadIdx.x >> 5, lane = threadIdx.x & 31;
    __syncthreads();
    if (lane == 0) { sbuf[w] = sv; sbuf[8 + w] = mv; }
    __syncthreads();
    if (threadIdx.x == 0) {
        float s = 0.f, m = -1e30f;
        for (int i = 0; i < 8; i++) { s += sbuf[i]; m = fmaxf(m, sbuf[8 + i]); }
        sbuf[0] = s; sbuf[8] = m;
    }
    __syncthreads();
    *outS = sbuf[0];
    *outM = sbuf[8];
}

template <int K, int NW>
__device__ __forceinline__ void poolStats(const float* yp, float* ws, float* wm) {
    float ts = 0.f, tm = -1e30f;
    for (int wdx = threadIdx.x; wdx < NW * NW; wdx += 256) {
        int wy = (wdx / NW) * K;
        int wx = (wdx - (wdx / NW) * NW) * K;
        float s = 0.f;
        #pragma unroll
        for (int dy = 0; dy < K; dy++)
            #pragma unroll
            for (int dx = 0; dx < K; dx++)
                s += yp[(wy + dy) * SSZ + wx + dx];
        ts += s;
        tm = fmaxf(tm, s);
    }
    *ws = ts;
    *wm = tm;
}

// grid (128, 32), 256 threads, dyn smem 50176 B
__global__ void k3_ypool(const float* __restrict__ rgb, const float* __restrict__ fre,
                         const float* __restrict__ lin1, const float* __restrict__ lin2) {
    extern __shared__ float yp[];
    __shared__ float sbuf[16];

    int c2 = blockIdx.x, b = blockIdx.y, tid = threadIdx.x;
    int path = (c2 >= 64);
    int c = c2 & 63;
    int base = (b * NC + c) * NSP;

    float mp, sc, of;
    if (!path) { mp = g_bn1[c];       sc = g_bn1[64 + c];  of = g_bn1[128 + c]; }
    else       { mp = g_bn1[192 + c]; sc = g_bn1[256 + c]; of = g_bn1[320 + c]; }
    float* ydst = path ? g_ylfs : g_yfad;

    // vectorized y pass: float4 loads of attn/rgb/fre (all 16B-aligned; NSP%4==0)
    const float4* a4p = (const float4*)(g_attn + base);
    const float4* r4p = (const float4*)(rgb + base);
    const float4* f4p = (const float4*)(fre + base);
    float4* y4g = (float4*)(ydst + base);
    float4* y4s = (float4*)yp;

    float ys = 0.f, yss = 0.f;
    #pragma unroll 2
    for (int i4 = tid; i4 < NSP / 4; i4 += 256) {
        float4 a4 = a4p[i4];
        float4 r4 = r4p[i4];
        float4 f4 = f4p[i4];
        float4 y4;
        if (!path) {
            y4.x = r4.x + (f4.x * a4.x - mp) * sc + of;
            y4.y = r4.y + (f4.y * a4.y - mp) * sc + of;
            y4.z = r4.z + (f4.z * a4.z - mp) * sc + of;
            y4.w = r4.w + (f4.w * a4.w - mp) * sc + of;
        } else {
            y4.x = f4.x + (r4.x * a4.x - mp) * sc + of;
            y4.y = f4.y + (r4.y * a4.y - mp) * sc + of;
            y4.z = f4.z + (r4.z * a4.z - mp) * sc + of;
            y4.w = f4.w + (r4.w * a4.w - mp) * sc + of;
        }
        y4s[i4] = y4;
        y4g[i4] = y4;
        ys += (y4.x + y4.y) + (y4.z + y4.w);
        yss += y4.x * y4.x + y4.y * y4.y + y4.z * y4.z + y4.w * y4.w;
    }
    {
        float bs, bm;
        blockReduceSumMax(ys, -1e30f, &bs, &bm, sbuf);
        if (tid == 0) g_ys[b * 128 + c2] = bs;
        blockReduceSumMax(yss, -1e30f, &bs, &bm, sbuf);
        if (tid == 0) g_yss[b * 128 + c2] = bs;
    }
    __syncthreads();

    float l10 = lin1[0], l11 = lin1[1], l12 = lin1[2];
    float l20 = lin2[0], l21 = lin2[1], l22 = lin2[2];
    float apv = 0.f, mpv = 0.f;
    float ws, wm, bs, bm;

    poolStats<3, 37>(yp, &ws, &wm);
    blockReduceSumMax(ws, wm, &bs, &bm, sbuf);
    apv += l10 * (bs / (37.f * 37.f * 9.f));
    mpv += l20 * (bm / 9.f);

    poolStats<5, 22>(yp, &ws, &wm);
    blockReduceSumMax(ws, wm, &bs, &bm, sbuf);
    apv += l11 * (bs / (22.f * 22.f * 25.f));
    mpv += l21 * (bm / 25.f);

    poolStats<7, 16>(yp, &ws, &wm);
    blockReduceSumMax(ws, wm, &bs, &bm, sbuf);
    apv += l12 * (bs / (16.f * 16.f * 49.f));
    mpv += l22 * (bm / 49.f);

    if (tid == 0) {
        g_ap[b * 128 + c2]    = apv;
        g_mpool[b * 128 + c2] = mpv;
    }
}

// ---------------- K4: MLP channel attention + analytic BN2 coefficients ----------------
__global__ void k4_mlp(const float* __restrict__ w1, const float* __restrict__ w2,
                       const float* __restrict__ rgb_cw, const float* __restrict__ rgb_cb,
                       const float* __restrict__ rgb_bg, const float* __restrict__ rgb_bb,
                       const float* __restrict__ fre_cw, const float* __restrict__ fre_cb,
                       const float* __restrict__ fre_bg, const float* __restrict__ fre_bb) {
    __shared__ float ca[NB][128];
    __shared__ float hsum[16];
    int tid = threadIdx.x;

    for (int b = 0; b < NB; b++) {
        if (tid < 16) {
            float ha = 0.f, hm = 0.f;
            for (int cth = 0; cth < 128; cth++) {
                float wv = w1[tid * 128 + cth];
                ha = fmaf(wv, g_ap[b * 128 + cth], ha);
                hm = fmaf(wv, g_mpool[b * 128 + cth], hm);
            }
            hsum[tid] = fmaxf(ha, 0.f) + fmaxf(hm, 0.f);
        }
        __syncthreads();
        float o = 0.f;
        #pragma unroll
        for (int r = 0; r < 16; r++) o = fmaf(w2[tid * 16 + r], hsum[r], o);
        ca[b][tid] = 1.0f / (1.0f + expf(-o));
        __syncthreads();
    }

    int path = (tid >= 64);
    int c = tid & 63;
    float cw = path ? fre_cw[c] : rgb_cw[c];
    float cb = path ? fre_cb[c] : rgb_cb[c];
    float bg = path ? fre_bg[c] : rgb_bg[c];
    float bb = path ? fre_bb[c] : rgb_bb[c];

    float s1 = 0.f, s2 = 0.f;
    for (int b = 0; b < NB; b++) {
        float cav = ca[b][tid];
        s1 = fmaf(cav, g_ys[b * 128 + tid], s1);
        s2 = fmaf(cav * cav, g_yss[b * 128 + tid], s2);
    }
    float meanz = (cw * s1) / NBN + cb;
    float Ezz = (cw * cw * s2 + 2.0f * cw * cb * s1) / NBN + cb * cb;
    float var = Ezz - meanz * meanz;
    float inv = rsqrtf(var + EPSV);
    g_Bcoef[tid] = (cb - meanz) * inv * bg + bb;
    for (int b = 0; b < NB; b++)
        g_Acoef[path * (NB * NC) + b * NC + c] = 1.0f + ca[b][tid] * cw * inv * bg;
}

// ---------------- K5: streaming output ----------------
__global__ void k5_out(float* __restrict__ out) {
    int c = blockIdx.x, b = blockIdx.y, path = blockIdx.z;
    int plane = (b * NC + c) * NSP;
    const float* y = (path ? g_ylfs : g_yfad) + plane;
    float A = g_Acoef[path * (NB * NC) + b * NC + c];
    float Bv = g_Bcoef[path * NC + c];
    float* o = out + (size_t)path * PLANE_TOT + plane;
    #pragma unroll 2
    for (int idx = threadIdx.x; idx < NSP / 4; idx += 256) {
        float4 v = ((const float4*)y)[idx];
        v.x = fmaf(v.x, A, Bv);
        v.y = fmaf(v.y, A, Bv);
        v.z = fmaf(v.z, A, Bv);
        v.w = fmaf(v.w, A, Bv);
        ((float4*)o)[idx] = v;
    }
}

// ---------------- launch ----------------
extern "C" void kernel_launch(void* const* d_in, const int* in_sizes, int n_in,
                              void* d_out, int out_size) {
    const float* rgb       = (const float*)d_in[0];
    const float* fre       = (const float*)d_in[1];
    const float* wq_fad    = (const float*)d_in[2];
    const float* bq_fad    = (const float*)d_in[3];
    const float* wq_lfs    = (const float*)d_in[4];
    const float* bq_lfs    = (const float*)d_in[5];
    const float* wk_fad    = (const float*)d_in[6];
    const float* bk_fad    = (const float*)d_in[7];
    const float* wk_lfs    = (const float*)d_in[8];
    const float* bk_lfs    = (const float*)d_in[9];
    const float* fad_gamma = (const float*)d_in[10];
    const float* lfs_gamma = (const float*)d_in[11];
    const float* fad_cw    = (const float*)d_in[12];
    const float* fad_bg    = (const float*)d_in[14];
    const float* fad_bb    = (const float*)d_in[15];
    const float* lfs_cw    = (const float*)d_in[16];
    const float* lfs_bg    = (const float*)d_in[18];
    const float* lfs_bb    = (const float*)d_in[19];
    const float* lin1_w    = (const float*)d_in[20];
    const float* lin2_w    = (const float*)d_in[21];
    const float* mlp_w1    = (const float*)d_in[22];
    const float* mlp_w2    = (const float*)d_in[23];
    const float* rgb_cw    = (const float*)d_in[24];
    const float* rgb_cb    = (const float*)d_in[25];
    const float* rgb_bg    = (const float*)d_in[26];
    const float* rgb_bb    = (const float*)d_in[27];
    const float* fre_cw    = (const float*)d_in[28];
    const float* fre_cb    = (const float*)d_in[29];
    const float* fre_bg    = (const float*)d_in[30];
    const float* fre_bb    = (const float*)d_in[31];

    cudaFuncSetAttribute(k1_proj,  cudaFuncAttributeMaxDynamicSharedMemorySize, 99328);
    cudaFuncSetAttribute(k2_attn,  cudaFuncAttributeMaxDynamicSharedMemorySize, 207872);
    cudaFuncSetAttribute(k3_ypool, cudaFuncAttributeMaxDynamicSharedMemorySize, 50176);

    // launch order chosen so k2_attn sits at capture index 3 (observed ncu skip = 3)
    k0a_zero<<<1, 128>>>();
    k0b_zero<<<1, 128>>>();
    k1_proj<<<dim3(196, NB), 256, 99328>>>(rgb, fre, wq_fad, bq_fad, wq_lfs, bq_lfs,
                                           wk_fad, bk_fad, wk_lfs, bk_lfs);
    k2_attn<<<2048, 256, 207872>>>(rgb, fre);
    k25_bn1<<<1, 64>>>(lfs_gamma, fad_gamma, fad_cw, fad_bg, fad_bb,
                       lfs_cw, lfs_bg, lfs_bb);
    k3_ypool<<<dim3(128, NB), 256, 50176>>>(rgb, fre, lin1_w, lin2_w);
    k4_mlp<<<1, 128>>>(mlp_w1, mlp_w2, rgb_cw, rgb_cb, rgb_bg, rgb_bb,
                       fre_cw, fre_cb, fre_bg, fre_bb);
    k5_out<<<dim3(NC, NB, 2), 256>>>((float*)d_out);
}